// round 1
// baseline (speedup 1.0000x reference)
#include <cuda_runtime.h>
#include <math.h>

#define N_NODES 100000
#define N_EDGES 500000
#define IN_C    128
#define EDGE_D  64
#define HEADS   4
#define HC      128

// Scratch (allocation-free rule: __device__ globals)
__device__ float g_Q[(size_t)N_NODES * HC];
__device__ float g_K[(size_t)N_NODES * HC];
__device__ float g_V[(size_t)N_NODES * HC];
__device__ float g_E[(size_t)N_EDGES * HC];    // 256 MB
__device__ float g_W[(size_t)N_EDGES * HEADS]; // exp(logit)
__device__ float g_D[(size_t)N_NODES * HEADS]; // softmax denominators

// ---------------------------------------------------------------------------
// Kernel 0: zero the denominators (graph replay must be deterministic)
// ---------------------------------------------------------------------------
__global__ void k_zero()
{
    int i = blockIdx.x * blockDim.x + threadIdx.x;
    if (i < N_NODES * HEADS) g_D[i] = 0.0f;
}

// ---------------------------------------------------------------------------
// Kernel 1: fused node projections.
//   blockIdx.y selects: 0->Q, 1->K, 2->V, 3->skip (written straight to out).
//   128-row x-tile + full 128x128 weight in smem, 16x16 threads, 8x8
//   strided microtile (rows ty+16i, cols tx+16j) => conflict-free LDS.128.
// ---------------------------------------------------------------------------
#define SX 132  // smem row stride (floats): mult of 4 (alignment), 132%32=4

__global__ void __launch_bounds__(256) k_proj(
    const float* __restrict__ x,
    const float* __restrict__ Wq, const float* __restrict__ bq,
    const float* __restrict__ Wk, const float* __restrict__ bk,
    const float* __restrict__ Wv, const float* __restrict__ bv,
    const float* __restrict__ Wsk, const float* __restrict__ bsk,
    float* __restrict__ out)
{
    extern __shared__ float sm[];
    float* xs = sm;              // [128][SX]
    float* ws = sm + 128 * SX;   // [128][SX]

    const int which = blockIdx.y;
    const float* W    = (which == 0) ? Wq : (which == 1) ? Wk : (which == 2) ? Wv : Wsk;
    const float* bias = (which == 0) ? bq : (which == 1) ? bk : (which == 2) ? bv : bsk;
    float* dst        = (which == 0) ? g_Q : (which == 1) ? g_K : (which == 2) ? g_V : out;

    const int row0 = blockIdx.x * 128;
    const int tid  = threadIdx.x;

    // Load x tile (coalesced float4, zero-fill tail rows)
    for (int t = tid; t < 128 * 32; t += 256) {
        int r = t >> 5, k4 = t & 31;
        float4 v = make_float4(0.f, 0.f, 0.f, 0.f);
        if (row0 + r < N_NODES)
            v = *(const float4*)(x + (size_t)(row0 + r) * 128 + k4 * 4);
        *(float4*)(xs + r * SX + k4 * 4) = v;
    }
    // Load weight matrix (row-major [c][k])
    for (int t = tid; t < 128 * 32; t += 256) {
        int c = t >> 5, k4 = t & 31;
        *(float4*)(ws + c * SX + k4 * 4) = *(const float4*)(W + c * 128 + k4 * 4);
    }
    __syncthreads();

    const int tx = tid & 15, ty = tid >> 4;

    float acc[8][8];
#pragma unroll
    for (int i = 0; i < 8; i++)
#pragma unroll
        for (int j = 0; j < 8; j++) acc[i][j] = 0.0f;

#pragma unroll 2
    for (int k = 0; k < 128; k += 4) {
        float4 a[8], b[8];
#pragma unroll
        for (int i = 0; i < 8; i++) a[i] = *(const float4*)(xs + (ty + 16 * i) * SX + k);
#pragma unroll
        for (int j = 0; j < 8; j++) b[j] = *(const float4*)(ws + (tx + 16 * j) * SX + k);
#pragma unroll
        for (int i = 0; i < 8; i++)
#pragma unroll
            for (int j = 0; j < 8; j++) {
                acc[i][j] += a[i].x * b[j].x;
                acc[i][j] += a[i].y * b[j].y;
                acc[i][j] += a[i].z * b[j].z;
                acc[i][j] += a[i].w * b[j].w;
            }
    }

#pragma unroll
    for (int i = 0; i < 8; i++) {
        int r = row0 + ty + 16 * i;
        if (r < N_NODES) {
#pragma unroll
            for (int j = 0; j < 8; j++) {
                int c = tx + 16 * j;
                dst[(size_t)r * 128 + c] = acc[i][j] + bias[c];
            }
        }
    }
}

// ---------------------------------------------------------------------------
// Kernel 2: edge GEMM e = edge_attr @ We^T fused with attention logits.
//   128-edge tile, same microtile as k_proj but K=64.
//   Epilogue: store e; p[h] = sum_c Q[dst][c]*(K[src][c]+e[c]);
//   reduce across the 16 tx lanes; exp + atomic denom accumulate.
// ---------------------------------------------------------------------------
#define SE 68   // mult of 4, 68%32=4

__global__ void __launch_bounds__(256) k_edge(
    const float* __restrict__ ea,
    const int*   __restrict__ eidx,
    const float* __restrict__ We)
{
    extern __shared__ float sm[];
    float* as = sm;              // [128][SE]
    float* ws = sm + 128 * SE;   // [128][SE]

    const int e0  = blockIdx.x * 128;
    const int tid = threadIdx.x;

    for (int t = tid; t < 128 * 16; t += 256) {
        int r = t >> 4, k4 = t & 15;
        float4 v = make_float4(0.f, 0.f, 0.f, 0.f);
        if (e0 + r < N_EDGES)
            v = *(const float4*)(ea + (size_t)(e0 + r) * 64 + k4 * 4);
        *(float4*)(as + r * SE + k4 * 4) = v;
    }
    for (int t = tid; t < 128 * 16; t += 256) {
        int c = t >> 4, k4 = t & 15;
        *(float4*)(ws + c * SE + k4 * 4) = *(const float4*)(We + c * 64 + k4 * 4);
    }
    __syncthreads();

    const int tx = tid & 15, ty = tid >> 4;

    float acc[8][8];
#pragma unroll
    for (int i = 0; i < 8; i++)
#pragma unroll
        for (int j = 0; j < 8; j++) acc[i][j] = 0.0f;

#pragma unroll 2
    for (int k = 0; k < 64; k += 4) {
        float4 a[8], b[8];
#pragma unroll
        for (int i = 0; i < 8; i++) a[i] = *(const float4*)(as + (ty + 16 * i) * SE + k);
#pragma unroll
        for (int j = 0; j < 8; j++) b[j] = *(const float4*)(ws + (tx + 16 * j) * SE + k);
#pragma unroll
        for (int i = 0; i < 8; i++)
#pragma unroll
            for (int j = 0; j < 8; j++) {
                acc[i][j] += a[i].x * b[j].x;
                acc[i][j] += a[i].y * b[j].y;
                acc[i][j] += a[i].z * b[j].z;
                acc[i][j] += a[i].w * b[j].w;
            }
    }

    // Epilogue: store e, accumulate per-head logit partials
    float p[8][4];
#pragma unroll
    for (int i = 0; i < 8; i++)
#pragma unroll
        for (int h = 0; h < 4; h++) p[i][h] = 0.0f;

#pragma unroll
    for (int i = 0; i < 8; i++) {
        int ed = e0 + ty + 16 * i;
        if (ed < N_EDGES) {
            int s = eidx[ed];
            int d = eidx[N_EDGES + ed];
            const float* Qr = g_Q + (size_t)d * 128;
            const float* Kr = g_K + (size_t)s * 128;
#pragma unroll
            for (int j = 0; j < 8; j++) {
                int c = tx + 16 * j;
                float ev = acc[i][j];
                g_E[(size_t)ed * 128 + c] = ev;
                p[i][j >> 1] += Qr[c] * (Kr[c] + ev);   // head = (tx+16j)/32 = j/2
            }
        }
    }

    // Reduce logit partials across the 16 tx lanes (stay within 16-lane group)
#pragma unroll
    for (int off = 1; off < 16; off <<= 1) {
#pragma unroll
        for (int i = 0; i < 8; i++)
#pragma unroll
            for (int h = 0; h < 4; h++)
                p[i][h] += __shfl_xor_sync(0xffffffffu, p[i][h], off);
    }

    if (tx == 0) {
#pragma unroll
        for (int i = 0; i < 8; i++) {
            int ed = e0 + ty + 16 * i;
            if (ed < N_EDGES) {
                int d = eidx[N_EDGES + ed];
#pragma unroll
                for (int h = 0; h < 4; h++) {
                    // exp(alpha) with no max-shift: the global max cancels in
                    // exp_a/denom exactly; logits are O(3) so no overflow.
                    float w = expf(p[i][h] * 0.17677669529663687f); // 1/sqrt(32)
                    g_W[(size_t)ed * 4 + h] = w;
                    atomicAdd(&g_D[(size_t)d * 4 + h], w);
                }
            }
        }
    }
}

// ---------------------------------------------------------------------------
// Kernel 3: message aggregation. One warp per edge (grid-stride).
//   msg = (V[src]+e) * alpha, vector-reduced into out[dst].
// ---------------------------------------------------------------------------
__global__ void __launch_bounds__(256) k_msg(
    const int* __restrict__ eidx, float* __restrict__ out)
{
    int warp = (blockIdx.x * blockDim.x + threadIdx.x) >> 5;
    int lane = threadIdx.x & 31;
    int nw   = (gridDim.x * blockDim.x) >> 5;
    int c0   = lane * 4;
    int h    = lane >> 3;

    for (int ed = warp; ed < N_EDGES; ed += nw) {
        int s = eidx[ed];
        int d = eidx[N_EDGES + ed];
        float4 e4 = *(const float4*)(g_E + (size_t)ed * 128 + c0);
        float4 v4 = *(const float4*)(g_V + (size_t)s * 128 + c0);
        float  w  = g_W[(size_t)ed * 4 + h];
        float  dn = g_D[(size_t)d * 4 + h];
        float  al = w / (dn + 1e-16f);
        float4 m  = make_float4((v4.x + e4.x) * al, (v4.y + e4.y) * al,
                                (v4.z + e4.z) * al, (v4.w + e4.w) * al);
        float* po = out + (size_t)d * 128 + c0;
        asm volatile("red.global.add.v4.f32 [%0], {%1,%2,%3,%4};"
                     :: "l"(po), "f"(m.x), "f"(m.y), "f"(m.z), "f"(m.w)
                     : "memory");
    }
}

// ---------------------------------------------------------------------------
extern "C" void kernel_launch(void* const* d_in, const int* in_sizes, int n_in,
                              void* d_out, int out_size)
{
    const float* x    = (const float*)d_in[0];
    const int*   eidx = (const int*)  d_in[1];
    const float* ea   = (const float*)d_in[2];
    const float* Wq   = (const float*)d_in[3];
    const float* bq   = (const float*)d_in[4];
    const float* Wk   = (const float*)d_in[5];
    const float* bk   = (const float*)d_in[6];
    const float* Wv   = (const float*)d_in[7];
    const float* bv   = (const float*)d_in[8];
    const float* We   = (const float*)d_in[9];
    const float* Wsk  = (const float*)d_in[10];
    const float* bsk  = (const float*)d_in[11];
    float* out = (float*)d_out;

    const int smem_proj = 2 * 128 * SX * (int)sizeof(float); // 135168
    const int smem_edge = 2 * 128 * SE * (int)sizeof(float); // 69632
    cudaFuncSetAttribute(k_proj, cudaFuncAttributeMaxDynamicSharedMemorySize, smem_proj);
    cudaFuncSetAttribute(k_edge, cudaFuncAttributeMaxDynamicSharedMemorySize, smem_edge);

    k_zero<<<(N_NODES * HEADS + 255) / 256, 256>>>();
    k_proj<<<dim3((N_NODES + 127) / 128, 4), 256, smem_proj>>>(
        x, Wq, bq, Wk, bk, Wv, bv, Wsk, bsk, out);
    k_edge<<<(N_EDGES + 127) / 128, 256, smem_edge>>>(ea, eidx, We);
    k_msg<<<2048, 256>>>(eidx, out);
}

// round 3
// speedup vs baseline: 1.0953x; 1.0953x over previous
#include <cuda_runtime.h>
#include <cuda_bf16.h>
#include <stdint.h>
#include <math.h>

#define N_NODES 100000
#define N_EDGES 500000

// Scratch (__device__ globals per allocation-free rule)
__device__ float g_Q[(size_t)N_NODES * 128];
__device__ float g_K[(size_t)N_NODES * 128];
__device__ float g_V[(size_t)N_NODES * 128];
__device__ float g_ACC[(size_t)N_NODES * 128];  // unnormalized message sums
__device__ float g_D[(size_t)N_NODES * 4];      // softmax denominators

// ---------------------------------------------------------------------------
// Portable tensor-core primitives (sm_80+; safe under the sm_103 family target)
// ---------------------------------------------------------------------------
__device__ __forceinline__ uint32_t smem_u32(const void* p) {
    uint32_t a;
    asm("{ .reg .u64 t; cvta.to.shared.u64 t, %1; cvt.u32.u64 %0, t; }"
        : "=r"(a) : "l"(p));
    return a;
}
#define LDSM4(r, addr) \
    asm volatile("ldmatrix.sync.aligned.m8n8.x4.shared.b16 {%0,%1,%2,%3}, [%4];" \
                 : "=r"((r)[0]), "=r"((r)[1]), "=r"((r)[2]), "=r"((r)[3]) \
                 : "r"(addr))
#define MMA_BF16(d, a, b0, b1) \
    asm volatile("mma.sync.aligned.m16n8k16.row.col.f32.bf16.bf16.f32 " \
                 "{%0,%1,%2,%3},{%4,%5,%6,%7},{%8,%9},{%0,%1,%2,%3};" \
                 : "+f"((d)[0]), "+f"((d)[1]), "+f"((d)[2]), "+f"((d)[3]) \
                 : "r"((a)[0]), "r"((a)[1]), "r"((a)[2]), "r"((a)[3]), \
                   "r"(b0), "r"(b1))

// ---------------------------------------------------------------------------
// fp32 -> bf16 hi/lo split into padded row-major smem (STR bf16 per row).
// ---------------------------------------------------------------------------
template <int KC, int STR>
__device__ __forceinline__ void cvt_tile(const float* __restrict__ src, int rows_valid,
                                         char* hi, char* lo, int tid) {
    const int PAIRS = 128 * (KC / 2);
    for (int t = tid; t < PAIRS; t += 256) {
        int r = t / (KC / 2);
        int c = (t % (KC / 2)) * 2;
        float2 v = make_float2(0.f, 0.f);
        if (r < rows_valid) v = *(const float2*)(src + (size_t)r * KC + c);
        __nv_bfloat16 h0 = __float2bfloat16(v.x);
        __nv_bfloat16 h1 = __float2bfloat16(v.y);
        __nv_bfloat16 l0 = __float2bfloat16(v.x - __bfloat162float(h0));
        __nv_bfloat16 l1 = __float2bfloat16(v.y - __bfloat162float(h1));
        uint32_t off = (uint32_t)(r * STR + c) * 2;
        __nv_bfloat162 hv; hv.x = h0; hv.y = h1;
        __nv_bfloat162 lv; lv.x = l0; lv.y = l1;
        *(__nv_bfloat162*)(hi + off) = hv;
        *(__nv_bfloat162*)(lo + off) = lv;
    }
}

// ---------------------------------------------------------------------------
// Kernel 0: zero accumulators (deterministic graph replay)
// ---------------------------------------------------------------------------
__global__ void k_zero() {
    int i = blockIdx.x * blockDim.x + threadIdx.x;
    if (i < N_NODES * 32) ((float4*)g_ACC)[i] = make_float4(0.f, 0.f, 0.f, 0.f);
    if (i < N_NODES)      ((float4*)g_D)[i]   = make_float4(0.f, 0.f, 0.f, 0.f);
}

// ---------------------------------------------------------------------------
// Kernel 1: node projections Q/K/V/skip. 128-row tile, 8 warps, each warp
// computes 32 rows x 64 cols via m16n8k16 bf16 HMMA, 3-pass hi/lo split.
// ---------------------------------------------------------------------------
#define PSTR 136                       // 272B rows: 17x16B -> conflict-free LDSM
#define PJ_T  (128 * PSTR * 2)         // 34816 B per tile
#define PJ_SMEM (4 * PJ_T)             // 139264 B

__global__ void __launch_bounds__(256) k_proj(
    const float* __restrict__ x,
    const float* __restrict__ Wq, const float* __restrict__ bq,
    const float* __restrict__ Wk, const float* __restrict__ bk,
    const float* __restrict__ Wv, const float* __restrict__ bv,
    const float* __restrict__ Wsk, const float* __restrict__ bsk,
    float* __restrict__ out)
{
    extern __shared__ char sm[];
    char* AHI = sm;            char* ALO = sm + PJ_T;
    char* BHI = sm + 2 * PJ_T; char* BLO = sm + 3 * PJ_T;
    const uint32_t sAhi = smem_u32(AHI), sAlo = smem_u32(ALO);
    const uint32_t sBhi = smem_u32(BHI), sBlo = smem_u32(BLO);

    const int tid = threadIdx.x, wid = tid >> 5, lane = tid & 31;
    const int row0 = blockIdx.x * 128;
    const int wr = (wid & 3) * 32, wc = (wid >> 2) * 64;

    // ldmatrix lane addressing
    const int grp = lane >> 3;
    const int lr  = ((grp & 1) << 3) + (lane & 7);
    const int lk  = (grp >> 1) << 3;

    cvt_tile<128, PSTR>(x + (size_t)row0 * 128, N_NODES - row0, AHI, ALO, tid);

    const float* Wptr[4] = {Wq, Wk, Wv, Wsk};
    const float* Bptr[4] = {bq, bk, bv, bsk};
    float*       Dptr[4] = {g_Q, g_K, g_V, out};

    for (int w = 0; w < 4; w++) {
        cvt_tile<128, PSTR>(Wptr[w], 128, BHI, BLO, tid);
        __syncthreads();

        float acc[2][8][4];
#pragma unroll
        for (int mi = 0; mi < 2; mi++)
#pragma unroll
            for (int nj = 0; nj < 8; nj++)
#pragma unroll
                for (int q = 0; q < 4; q++) acc[mi][nj][q] = 0.f;

#pragma unroll
        for (int p = 0; p < 3; p++) {
            const uint32_t sA = (p < 2) ? sAhi : sAlo;
            const uint32_t sB = (p == 1) ? sBlo : sBhi;
#pragma unroll
            for (int k = 0; k < 128; k += 16) {
                uint32_t a[2][4], b[4][4];
#pragma unroll
                for (int mi = 0; mi < 2; mi++)
                    LDSM4(a[mi], sA + ((wr + mi * 16 + lr) * PSTR + k + lk) * 2);
#pragma unroll
                for (int nt = 0; nt < 4; nt++)
                    LDSM4(b[nt], sB + ((wc + nt * 16 + lr) * PSTR + k + lk) * 2);
#pragma unroll
                for (int mi = 0; mi < 2; mi++)
#pragma unroll
                    for (int nt = 0; nt < 4; nt++) {
                        MMA_BF16(acc[mi][nt * 2 + 0], a[mi], b[nt][0], b[nt][2]);
                        MMA_BF16(acc[mi][nt * 2 + 1], a[mi], b[nt][1], b[nt][3]);
                    }
            }
        }

        // Epilogue: d0,d1 -> row tr, cols tc2,tc2+1; d2,d3 -> row tr+8
        const int tr = lane >> 2, tc2 = (lane & 3) * 2;
        const float* bias = Bptr[w];
        float* dst = Dptr[w];
#pragma unroll
        for (int mi = 0; mi < 2; mi++) {
            int r = row0 + wr + mi * 16 + tr;
#pragma unroll
            for (int nj = 0; nj < 8; nj++) {
                int col = wc + nj * 8 + tc2;
                float2 b2 = *(const float2*)(bias + col);
                if (r < N_NODES) {
                    float2 o = make_float2(acc[mi][nj][0] + b2.x, acc[mi][nj][1] + b2.y);
                    *(float2*)(dst + (size_t)r * 128 + col) = o;
                }
                if (r + 8 < N_NODES) {
                    float2 o = make_float2(acc[mi][nj][2] + b2.x, acc[mi][nj][3] + b2.y);
                    *(float2*)(dst + (size_t)(r + 8) * 128 + col) = o;
                }
            }
        }
        __syncthreads();   // B tiles fully consumed before next convert
    }
}

// ---------------------------------------------------------------------------
// Kernel 2: edge GEMM e = edge_attr @ We^T (bf16-split HMMA) fused with
// logits, exp, denom atomics and unnormalized message accumulation.
// ---------------------------------------------------------------------------
#define ESTR 72                        // 144B rows: 9x16B -> conflict-free LDSM
#define EG_T (128 * ESTR * 2)          // 18432 B per tile
#define EG_SMEM (4 * EG_T)             // 73728 B; e-tile (67584 B) reuses region

__global__ void __launch_bounds__(256) k_edge(
    const float* __restrict__ ea,
    const int*   __restrict__ eidx,
    const float* __restrict__ We)
{
    extern __shared__ char sm[];
    char* AHI = sm;            char* ALO = sm + EG_T;
    char* BHI = sm + 2 * EG_T; char* BLO = sm + 3 * EG_T;
    const uint32_t sAhi = smem_u32(AHI), sAlo = smem_u32(ALO);
    const uint32_t sBhi = smem_u32(BHI), sBlo = smem_u32(BLO);
    float* es = (float*)sm;            // e tile [128][132] fp32, reused region

    const int tid = threadIdx.x, wid = tid >> 5, lane = tid & 31;
    const int e0 = blockIdx.x * 128;
    const int wr = (wid & 3) * 32, wc = (wid >> 2) * 64;
    const int grp = lane >> 3;
    const int lr  = ((grp & 1) << 3) + (lane & 7);
    const int lk  = (grp >> 1) << 3;

    cvt_tile<64, ESTR>(ea + (size_t)e0 * 64, N_EDGES - e0, AHI, ALO, tid);
    cvt_tile<64, ESTR>(We, 128, BHI, BLO, tid);
    __syncthreads();

    float acc[2][8][4];
#pragma unroll
    for (int mi = 0; mi < 2; mi++)
#pragma unroll
        for (int nj = 0; nj < 8; nj++)
#pragma unroll
            for (int q = 0; q < 4; q++) acc[mi][nj][q] = 0.f;

#pragma unroll
    for (int p = 0; p < 3; p++) {
        const uint32_t sA = (p < 2) ? sAhi : sAlo;
        const uint32_t sB = (p == 1) ? sBlo : sBhi;
#pragma unroll
        for (int k = 0; k < 64; k += 16) {
            uint32_t a[2][4], b[4][4];
#pragma unroll
            for (int mi = 0; mi < 2; mi++)
                LDSM4(a[mi], sA + ((wr + mi * 16 + lr) * ESTR + k + lk) * 2);
#pragma unroll
            for (int nt = 0; nt < 4; nt++)
                LDSM4(b[nt], sB + ((wc + nt * 16 + lr) * ESTR + k + lk) * 2);
#pragma unroll
            for (int mi = 0; mi < 2; mi++)
#pragma unroll
                for (int nt = 0; nt < 4; nt++) {
                    MMA_BF16(acc[mi][nt * 2 + 0], a[mi], b[nt][0], b[nt][2]);
                    MMA_BF16(acc[mi][nt * 2 + 1], a[mi], b[nt][1], b[nt][3]);
                }
        }
    }
    __syncthreads();   // all smem reads done; safe to overwrite with e tile

    // Spill e tile to smem fp32 [128][132]
    {
        const int tr = lane >> 2, tc2 = (lane & 3) * 2;
#pragma unroll
        for (int mi = 0; mi < 2; mi++) {
            int r = wr + mi * 16 + tr;
#pragma unroll
            for (int nj = 0; nj < 8; nj++) {
                int col = wc + nj * 8 + tc2;
                *(float2*)(es + r * 132 + col) =
                    make_float2(acc[mi][nj][0], acc[mi][nj][1]);
                *(float2*)(es + (r + 8) * 132 + col) =
                    make_float2(acc[mi][nj][2], acc[mi][nj][3]);
            }
        }
    }
    __syncthreads();

    // Epilogue: 2 threads per edge, each owns a 64-col half (= 2 heads).
    const int el = tid >> 1, half = tid & 1;
    const int ed = e0 + el;
    if (ed < N_EDGES) {
        const int s = eidx[ed];
        const int d = eidx[N_EDGES + ed];
        const float4* Qp = (const float4*)(g_Q + (size_t)d * 128 + half * 64);
        const float4* Kp = (const float4*)(g_K + (size_t)s * 128 + half * 64);
        const float4* Vp = (const float4*)(g_V + (size_t)s * 128 + half * 64);
        const float4* Ep = (const float4*)(es + el * 132 + half * 64);

        float p0 = 0.f, p1 = 0.f;
        float4 e4s[16];
#pragma unroll
        for (int j = 0; j < 16; j++) {
            float4 e4 = Ep[j]; e4s[j] = e4;
            float4 q4 = Qp[j], k4 = Kp[j];
            float t = q4.x * (k4.x + e4.x) + q4.y * (k4.y + e4.y) +
                      q4.z * (k4.z + e4.z) + q4.w * (k4.w + e4.w);
            if (j < 8) p0 += t; else p1 += t;
        }
        // Global max-shift cancels exactly in exp/denom; logits are O(3).
        const float sc = 0.17677669529663687f;  // 1/sqrt(32)
        float w0 = expf(p0 * sc), w1 = expf(p1 * sc);
        atomicAdd(&g_D[(size_t)d * 4 + half * 2 + 0], w0);
        atomicAdd(&g_D[(size_t)d * 4 + half * 2 + 1], w1);

        float* ap = g_ACC + (size_t)d * 128 + half * 64;
#pragma unroll
        for (int j = 0; j < 16; j++) {
            float4 v4 = Vp[j], e4 = e4s[j];
            float wv = (j < 8) ? w0 : w1;
            float mx = (v4.x + e4.x) * wv, my = (v4.y + e4.y) * wv;
            float mz = (v4.z + e4.z) * wv, mw = (v4.w + e4.w) * wv;
            asm volatile("red.global.add.v4.f32 [%0], {%1,%2,%3,%4};"
                         :: "l"(ap + 4 * j), "f"(mx), "f"(my), "f"(mz), "f"(mw)
                         : "memory");
        }
    }
}

// ---------------------------------------------------------------------------
// Kernel 3: out += g_ACC / (denom + 1e-16)   (skip already in out from k_proj)
// ---------------------------------------------------------------------------
__global__ void k_fin(float* __restrict__ out) {
    int i = blockIdx.x * blockDim.x + threadIdx.x;
    if (i < N_NODES * 32) {
        int n = i >> 5, q = i & 31, h = q >> 3;
        float inv = 1.f / (g_D[(size_t)n * 4 + h] + 1e-16f);
        float4 a = ((const float4*)g_ACC)[i];
        float4 o = ((float4*)out)[i];
        o.x += a.x * inv; o.y += a.y * inv;
        o.z += a.z * inv; o.w += a.w * inv;
        ((float4*)out)[i] = o;
    }
}

// ---------------------------------------------------------------------------
extern "C" void kernel_launch(void* const* d_in, const int* in_sizes, int n_in,
                              void* d_out, int out_size)
{
    const float* x    = (const float*)d_in[0];
    const int*   eidx = (const int*)  d_in[1];
    const float* ea   = (const float*)d_in[2];
    const float* Wq   = (const float*)d_in[3];
    const float* bq   = (const float*)d_in[4];
    const float* Wk   = (const float*)d_in[5];
    const float* bk   = (const float*)d_in[6];
    const float* Wv   = (const float*)d_in[7];
    const float* bv   = (const float*)d_in[8];
    const float* We   = (const float*)d_in[9];
    const float* Wsk  = (const float*)d_in[10];
    const float* bsk  = (const float*)d_in[11];
    float* out = (float*)d_out;

    cudaFuncSetAttribute(k_proj, cudaFuncAttributeMaxDynamicSharedMemorySize, PJ_SMEM);
    cudaFuncSetAttribute(k_edge, cudaFuncAttributeMaxDynamicSharedMemorySize, EG_SMEM);

    k_zero<<<(N_NODES * 32 + 255) / 256, 256>>>();
    k_proj<<<(N_NODES + 127) / 128, 256, PJ_SMEM>>>(
        x, Wq, bq, Wk, bk, Wv, bv, Wsk, bsk, out);
    k_edge<<<(N_EDGES + 127) / 128, 256, EG_SMEM>>>(ea, eidx, We);
    k_fin<<<(N_NODES * 32 + 255) / 256, 256>>>(out);
}

// round 4
// speedup vs baseline: 1.2926x; 1.1802x over previous
#include <cuda_runtime.h>
#include <cuda_bf16.h>
#include <stdint.h>
#include <math.h>

#define N_NODES 100000
#define N_EDGES 500000

// Scratch (__device__ globals per allocation-free rule)
__device__ float g_Q[(size_t)N_NODES * 128];
__device__ float g_K[(size_t)N_NODES * 128];
__device__ float g_V[(size_t)N_NODES * 128];
__device__ float g_ACC[(size_t)N_NODES * 128];  // unnormalized message sums
__device__ float g_D[(size_t)N_NODES * 4];      // softmax denominators

// ---------------------------------------------------------------------------
// Portable tensor-core primitives (sm_80+; safe under the sm_103 family target)
// ---------------------------------------------------------------------------
__device__ __forceinline__ uint32_t smem_u32(const void* p) {
    uint32_t a;
    asm("{ .reg .u64 t; cvta.to.shared.u64 t, %1; cvt.u32.u64 %0, t; }"
        : "=r"(a) : "l"(p));
    return a;
}
#define LDSM4(r, addr) \
    asm volatile("ldmatrix.sync.aligned.m8n8.x4.shared.b16 {%0,%1,%2,%3}, [%4];" \
                 : "=r"((r)[0]), "=r"((r)[1]), "=r"((r)[2]), "=r"((r)[3]) \
                 : "r"(addr))
#define MMA_BF16(d, a, b0, b1) \
    asm volatile("mma.sync.aligned.m16n8k16.row.col.f32.bf16.bf16.f32 " \
                 "{%0,%1,%2,%3},{%4,%5,%6,%7},{%8,%9},{%0,%1,%2,%3};" \
                 : "+f"((d)[0]), "+f"((d)[1]), "+f"((d)[2]), "+f"((d)[3]) \
                 : "r"((a)[0]), "r"((a)[1]), "r"((a)[2]), "r"((a)[3]), \
                   "r"(b0), "r"(b1))

// ---------------------------------------------------------------------------
// fp32 -> bf16 hi/lo split into padded row-major smem (STR bf16 per row).
// ---------------------------------------------------------------------------
template <int ROWS, int KC, int STR>
__device__ __forceinline__ void cvt_tile(const float* __restrict__ src, int rows_valid,
                                         char* hi, char* lo, int tid) {
    const int PAIRS = ROWS * (KC / 2);
    for (int t = tid; t < PAIRS; t += 256) {
        int r = t / (KC / 2);
        int c = (t % (KC / 2)) * 2;
        float2 v = make_float2(0.f, 0.f);
        if (r < rows_valid) v = *(const float2*)(src + (size_t)r * KC + c);
        __nv_bfloat16 h0 = __float2bfloat16(v.x);
        __nv_bfloat16 h1 = __float2bfloat16(v.y);
        __nv_bfloat16 l0 = __float2bfloat16(v.x - __bfloat162float(h0));
        __nv_bfloat16 l1 = __float2bfloat16(v.y - __bfloat162float(h1));
        uint32_t off = (uint32_t)(r * STR + c) * 2;
        __nv_bfloat162 hv; hv.x = h0; hv.y = h1;
        __nv_bfloat162 lv; lv.x = l0; lv.y = l1;
        *(__nv_bfloat162*)(hi + off) = hv;
        *(__nv_bfloat162*)(lo + off) = lv;
    }
}

// ---------------------------------------------------------------------------
// Kernel 0: zero accumulators (deterministic graph replay)
// ---------------------------------------------------------------------------
__global__ void k_zero() {
    int i = blockIdx.x * blockDim.x + threadIdx.x;
    if (i < N_NODES * 32) ((float4*)g_ACC)[i] = make_float4(0.f, 0.f, 0.f, 0.f);
    if (i < N_NODES)      ((float4*)g_D)[i]   = make_float4(0.f, 0.f, 0.f, 0.f);
}

// ---------------------------------------------------------------------------
// Kernel 1: node projections Q/K/V/skip. 64-row tile (2 CTAs/SM), 8 warps in
// a 2x4 grid; each warp 32 rows x 32 cols via m16n8k16 bf16 HMMA, 3-pass split.
// ---------------------------------------------------------------------------
#define PSTR 136                        // 272B rows: 17x16B -> conflict-free LDSM
#define PJ_AT (64 * PSTR * 2)           // 17408 B
#define PJ_BT (128 * PSTR * 2)          // 34816 B
#define PJ_SMEM (2 * PJ_AT + 2 * PJ_BT) // 104448 B -> 2 CTAs/SM

__global__ void __launch_bounds__(256, 2) k_proj(
    const float* __restrict__ x,
    const float* __restrict__ Wq, const float* __restrict__ bq,
    const float* __restrict__ Wk, const float* __restrict__ bk,
    const float* __restrict__ Wv, const float* __restrict__ bv,
    const float* __restrict__ Wsk, const float* __restrict__ bsk,
    float* __restrict__ out)
{
    extern __shared__ char sm[];
    char* AHI = sm;                     char* ALO = sm + PJ_AT;
    char* BHI = sm + 2 * PJ_AT;         char* BLO = sm + 2 * PJ_AT + PJ_BT;
    const uint32_t sAhi = smem_u32(AHI), sAlo = smem_u32(ALO);
    const uint32_t sBhi = smem_u32(BHI), sBlo = smem_u32(BLO);

    const int tid = threadIdx.x, wid = tid >> 5, lane = tid & 31;
    const int row0 = blockIdx.x * 64;
    const int wr = (wid & 1) * 32, wc = (wid >> 1) * 32;

    // ldmatrix lane addressing
    const int grp = lane >> 3;
    const int lr  = ((grp & 1) << 3) + (lane & 7);
    const int lk  = (grp >> 1) << 3;

    cvt_tile<64, 128, PSTR>(x + (size_t)row0 * 128, N_NODES - row0, AHI, ALO, tid);

    const float* Wptr[4] = {Wq, Wk, Wv, Wsk};
    const float* Bptr[4] = {bq, bk, bv, bsk};
    float*       Dptr[4] = {g_Q, g_K, g_V, out};

    for (int w = 0; w < 4; w++) {
        cvt_tile<128, 128, PSTR>(Wptr[w], 128, BHI, BLO, tid);
        __syncthreads();

        float acc[2][4][4];
#pragma unroll
        for (int mi = 0; mi < 2; mi++)
#pragma unroll
            for (int nj = 0; nj < 4; nj++)
#pragma unroll
                for (int q = 0; q < 4; q++) acc[mi][nj][q] = 0.f;

#pragma unroll
        for (int p = 0; p < 3; p++) {
            const uint32_t sA = (p < 2) ? sAhi : sAlo;
            const uint32_t sB = (p == 1) ? sBlo : sBhi;
#pragma unroll
            for (int k = 0; k < 128; k += 16) {
                uint32_t a[2][4], b[2][4];
#pragma unroll
                for (int mi = 0; mi < 2; mi++)
                    LDSM4(a[mi], sA + ((wr + mi * 16 + lr) * PSTR + k + lk) * 2);
#pragma unroll
                for (int nt = 0; nt < 2; nt++)
                    LDSM4(b[nt], sB + ((wc + nt * 16 + lr) * PSTR + k + lk) * 2);
#pragma unroll
                for (int mi = 0; mi < 2; mi++)
#pragma unroll
                    for (int nt = 0; nt < 2; nt++) {
                        MMA_BF16(acc[mi][nt * 2 + 0], a[mi], b[nt][0], b[nt][2]);
                        MMA_BF16(acc[mi][nt * 2 + 1], a[mi], b[nt][1], b[nt][3]);
                    }
            }
        }

        const int tr = lane >> 2, tc2 = (lane & 3) * 2;
        const float* bias = Bptr[w];
        float* dst = Dptr[w];
#pragma unroll
        for (int mi = 0; mi < 2; mi++) {
            int r = row0 + wr + mi * 16 + tr;
#pragma unroll
            for (int nj = 0; nj < 4; nj++) {
                int col = wc + nj * 8 + tc2;
                float2 b2 = *(const float2*)(bias + col);
                if (r < N_NODES) {
                    float2 o = make_float2(acc[mi][nj][0] + b2.x, acc[mi][nj][1] + b2.y);
                    *(float2*)(dst + (size_t)r * 128 + col) = o;
                }
                if (r + 8 < N_NODES) {
                    float2 o = make_float2(acc[mi][nj][2] + b2.x, acc[mi][nj][3] + b2.y);
                    *(float2*)(dst + (size_t)(r + 8) * 128 + col) = o;
                }
            }
        }
        __syncthreads();
    }
}

// ---------------------------------------------------------------------------
// Kernel 2: edge GEMM e = edge_attr @ We^T (bf16-split HMMA) fused with
// logits, exp, denom atomics and unnormalized message accumulation.
// Epilogue: 8 lanes per edge -> every LDG.128 / RED.128 is one coalesced
// 128B line per edge (nL=4/warp instead of 32).
// ---------------------------------------------------------------------------
#define ESTR 72                        // 144B rows: 9x16B -> conflict-free LDSM
#define EG_T (128 * ESTR * 2)          // 18432 B per tile
#define EG_SMEM (4 * EG_T)             // 73728 B; e-tile (67584 B) reuses region

__global__ void __launch_bounds__(256) k_edge(
    const float* __restrict__ ea,
    const int*   __restrict__ eidx,
    const float* __restrict__ We)
{
    extern __shared__ char sm[];
    char* AHI = sm;            char* ALO = sm + EG_T;
    char* BHI = sm + 2 * EG_T; char* BLO = sm + 3 * EG_T;
    const uint32_t sAhi = smem_u32(AHI), sAlo = smem_u32(ALO);
    const uint32_t sBhi = smem_u32(BHI), sBlo = smem_u32(BLO);
    float* es = (float*)sm;            // e tile [128][132] fp32, reused region

    const int tid = threadIdx.x, wid = tid >> 5, lane = tid & 31;
    const int e0 = blockIdx.x * 128;
    const int wr = (wid & 3) * 32, wc = (wid >> 2) * 64;
    const int grp = lane >> 3;
    const int lr  = ((grp & 1) << 3) + (lane & 7);
    const int lk  = (grp >> 1) << 3;

    cvt_tile<128, 64, ESTR>(ea + (size_t)e0 * 64, N_EDGES - e0, AHI, ALO, tid);
    cvt_tile<128, 64, ESTR>(We, 128, BHI, BLO, tid);
    __syncthreads();

    float acc[2][8][4];
#pragma unroll
    for (int mi = 0; mi < 2; mi++)
#pragma unroll
        for (int nj = 0; nj < 8; nj++)
#pragma unroll
            for (int q = 0; q < 4; q++) acc[mi][nj][q] = 0.f;

#pragma unroll
    for (int p = 0; p < 3; p++) {
        const uint32_t sA = (p < 2) ? sAhi : sAlo;
        const uint32_t sB = (p == 1) ? sBlo : sBhi;
#pragma unroll
        for (int k = 0; k < 64; k += 16) {
            uint32_t a[2][4], b[4][4];
#pragma unroll
            for (int mi = 0; mi < 2; mi++)
                LDSM4(a[mi], sA + ((wr + mi * 16 + lr) * ESTR + k + lk) * 2);
#pragma unroll
            for (int nt = 0; nt < 4; nt++)
                LDSM4(b[nt], sB + ((wc + nt * 16 + lr) * ESTR + k + lk) * 2);
#pragma unroll
            for (int mi = 0; mi < 2; mi++)
#pragma unroll
                for (int nt = 0; nt < 4; nt++) {
                    MMA_BF16(acc[mi][nt * 2 + 0], a[mi], b[nt][0], b[nt][2]);
                    MMA_BF16(acc[mi][nt * 2 + 1], a[mi], b[nt][1], b[nt][3]);
                }
        }
    }
    __syncthreads();   // all smem reads done; safe to overwrite with e tile

    // Spill e tile to smem fp32 [128][132]
    {
        const int tr = lane >> 2, tc2 = (lane & 3) * 2;
#pragma unroll
        for (int mi = 0; mi < 2; mi++) {
            int r = wr + mi * 16 + tr;
#pragma unroll
            for (int nj = 0; nj < 8; nj++) {
                int col = wc + nj * 8 + tc2;
                *(float2*)(es + r * 132 + col) =
                    make_float2(acc[mi][nj][0], acc[mi][nj][1]);
                *(float2*)(es + (r + 8) * 132 + col) =
                    make_float2(acc[mi][nj][2], acc[mi][nj][3]);
            }
        }
    }
    __syncthreads();

    // Epilogue: 8 lanes per edge (4 edges per warp, 4 iterations).
    // Lane li owns float4 at column j*32 + li*4 for j=0..3 (head j).
    const int sub = lane >> 3;   // edge-in-group 0..3
    const int li  = lane & 7;
    const float sc = 0.17677669529663687f;  // 1/sqrt(32)

#pragma unroll
    for (int it = 0; it < 4; it++) {
        const int el = wid * 16 + it * 4 + sub;
        const int ed = e0 + el;
        const bool valid = ed < N_EDGES;
        int s = 0, d = 0;
        if (valid) { s = eidx[ed]; d = eidx[N_EDGES + ed]; }

        float4 e4[4], v4[4];
        float p[4];
#pragma unroll
        for (int j = 0; j < 4; j++) {
            e4[j] = *(const float4*)(es + el * 132 + j * 32 + li * 4);
            p[j] = 0.f;
        }
        if (valid) {
            const float* Qr = g_Q + (size_t)d * 128;
            const float* Kr = g_K + (size_t)s * 128;
            const float* Vr = g_V + (size_t)s * 128;
#pragma unroll
            for (int j = 0; j < 4; j++) {
                int c = j * 32 + li * 4;
                float4 q4 = *(const float4*)(Qr + c);
                float4 k4 = *(const float4*)(Kr + c);
                v4[j] = *(const float4*)(Vr + c);
                p[j] = q4.x * (k4.x + e4[j].x) + q4.y * (k4.y + e4[j].y) +
                       q4.z * (k4.z + e4[j].z) + q4.w * (k4.w + e4[j].w);
            }
        }
        // Reduce logits across the 8 lanes of this edge
#pragma unroll
        for (int off = 1; off < 8; off <<= 1) {
#pragma unroll
            for (int j = 0; j < 4; j++)
                p[j] += __shfl_xor_sync(0xffffffffu, p[j], off);
        }
        // Global max-shift cancels exactly in exp/denom; logits are O(3).
        float w[4];
#pragma unroll
        for (int j = 0; j < 4; j++) w[j] = __expf(p[j] * sc);

        if (valid && li == 0) {
            atomicAdd(&g_D[(size_t)d * 4 + 0], w[0]);
            atomicAdd(&g_D[(size_t)d * 4 + 1], w[1]);
            atomicAdd(&g_D[(size_t)d * 4 + 2], w[2]);
            atomicAdd(&g_D[(size_t)d * 4 + 3], w[3]);
        }
        if (valid) {
            float* ap = g_ACC + (size_t)d * 128;
#pragma unroll
            for (int j = 0; j < 4; j++) {
                float mx = (v4[j].x + e4[j].x) * w[j];
                float my = (v4[j].y + e4[j].y) * w[j];
                float mz = (v4[j].z + e4[j].z) * w[j];
                float mw = (v4[j].w + e4[j].w) * w[j];
                asm volatile("red.global.add.v4.f32 [%0], {%1,%2,%3,%4};"
                             :: "l"(ap + j * 32 + li * 4),
                                "f"(mx), "f"(my), "f"(mz), "f"(mw)
                             : "memory");
            }
        }
    }
}

// ---------------------------------------------------------------------------
// Kernel 3: out += g_ACC / (denom + 1e-16)   (skip already in out from k_proj)
// ---------------------------------------------------------------------------
__global__ void k_fin(float* __restrict__ out) {
    int i = blockIdx.x * blockDim.x + threadIdx.x;
    if (i < N_NODES * 32) {
        int n = i >> 5, q = i & 31, h = q >> 3;
        float inv = 1.f / (g_D[(size_t)n * 4 + h] + 1e-16f);
        float4 a = ((const float4*)g_ACC)[i];
        float4 o = ((float4*)out)[i];
        o.x += a.x * inv; o.y += a.y * inv;
        o.z += a.z * inv; o.w += a.w * inv;
        ((float4*)out)[i] = o;
    }
}

// ---------------------------------------------------------------------------
extern "C" void kernel_launch(void* const* d_in, const int* in_sizes, int n_in,
                              void* d_out, int out_size)
{
    const float* x    = (const float*)d_in[0];
    const int*   eidx = (const int*)  d_in[1];
    const float* ea   = (const float*)d_in[2];
    const float* Wq   = (const float*)d_in[3];
    const float* bq   = (const float*)d_in[4];
    const float* Wk   = (const float*)d_in[5];
    const float* bk   = (const float*)d_in[6];
    const float* Wv   = (const float*)d_in[7];
    const float* bv   = (const float*)d_in[8];
    const float* We   = (const float*)d_in[9];
    const float* Wsk  = (const float*)d_in[10];
    const float* bsk  = (const float*)d_in[11];
    float* out = (float*)d_out;

    cudaFuncSetAttribute(k_proj, cudaFuncAttributeMaxDynamicSharedMemorySize, PJ_SMEM);
    cudaFuncSetAttribute(k_edge, cudaFuncAttributeMaxDynamicSharedMemorySize, EG_SMEM);

    k_zero<<<(N_NODES * 32 + 255) / 256, 256>>>();
    k_proj<<<(N_NODES + 63) / 64, 256, PJ_SMEM>>>(
        x, Wq, bq, Wk, bk, Wv, bv, Wsk, bsk, out);
    k_edge<<<(N_EDGES + 127) / 128, 256, EG_SMEM>>>(ea, eidx, We);
    k_fin<<<(N_NODES * 32 + 255) / 256, 256>>>(out);
}

// round 5
// speedup vs baseline: 1.9953x; 1.5436x over previous
#include <cuda_runtime.h>
#include <cuda_bf16.h>
#include <stdint.h>
#include <math.h>

#define N_NODES 100000
#define N_EDGES 500000

// Scratch (__device__ globals per allocation-free rule)
__device__ float g_Q[(size_t)N_NODES * 128];
__device__ float g_K[(size_t)N_NODES * 128];
__device__ float g_V[(size_t)N_NODES * 128];
__device__ float g_ACC[(size_t)N_NODES * 128];  // unnormalized message sums
__device__ float g_D[(size_t)N_NODES * 4];      // softmax denominators

#define PSTR 136   // proj smem row stride (bf16): 17x16B -> conflict-free LDSM
#define ESTR 72    // edge smem row stride (bf16): 9x16B  -> conflict-free LDSM

// Pre-converted weights (hi/lo bf16, pre-padded to smem strides)
__device__ __align__(16) __nv_bfloat16 g_Whi[4][128 * PSTR];
__device__ __align__(16) __nv_bfloat16 g_Wlo[4][128 * PSTR];
__device__ __align__(16) __nv_bfloat16 g_WEhi[128 * ESTR];
__device__ __align__(16) __nv_bfloat16 g_WElo[128 * ESTR];

// ---------------------------------------------------------------------------
// Portable tensor-core primitives (sm_80+; safe under the sm_103 family target)
// ---------------------------------------------------------------------------
__device__ __forceinline__ uint32_t smem_u32(const void* p) {
    uint32_t a;
    asm("{ .reg .u64 t; cvta.to.shared.u64 t, %1; cvt.u32.u64 %0, t; }"
        : "=r"(a) : "l"(p));
    return a;
}
#define LDSM4(r, addr) \
    asm volatile("ldmatrix.sync.aligned.m8n8.x4.shared.b16 {%0,%1,%2,%3}, [%4];" \
                 : "=r"((r)[0]), "=r"((r)[1]), "=r"((r)[2]), "=r"((r)[3]) \
                 : "r"(addr))
#define MMA_BF16(d, a, b0, b1) \
    asm volatile("mma.sync.aligned.m16n8k16.row.col.f32.bf16.bf16.f32 " \
                 "{%0,%1,%2,%3},{%4,%5,%6,%7},{%8,%9},{%0,%1,%2,%3};" \
                 : "+f"((d)[0]), "+f"((d)[1]), "+f"((d)[2]), "+f"((d)[3]) \
                 : "r"((a)[0]), "r"((a)[1]), "r"((a)[2]), "r"((a)[3]), \
                   "r"(b0), "r"(b1))

// ---------------------------------------------------------------------------
// fp32 -> bf16 hi/lo split into padded row-major smem (STR bf16 per row).
// float4-granularity loads.
// ---------------------------------------------------------------------------
template <int ROWS, int KC, int STR>
__device__ __forceinline__ void cvt_tile(const float* __restrict__ src, int rows_valid,
                                         char* hi, char* lo, int tid) {
    const int QUADS = ROWS * (KC / 4);
    for (int t = tid; t < QUADS; t += 256) {
        int r = t / (KC / 4);
        int c = (t % (KC / 4)) * 4;
        float4 v = make_float4(0.f, 0.f, 0.f, 0.f);
        if (r < rows_valid) v = *(const float4*)(src + (size_t)r * KC + c);
        __nv_bfloat16 h0 = __float2bfloat16(v.x), h1 = __float2bfloat16(v.y);
        __nv_bfloat16 h2 = __float2bfloat16(v.z), h3 = __float2bfloat16(v.w);
        __nv_bfloat16 l0 = __float2bfloat16(v.x - __bfloat162float(h0));
        __nv_bfloat16 l1 = __float2bfloat16(v.y - __bfloat162float(h1));
        __nv_bfloat16 l2 = __float2bfloat16(v.z - __bfloat162float(h2));
        __nv_bfloat16 l3 = __float2bfloat16(v.w - __bfloat162float(h3));
        uint32_t off = (uint32_t)(r * STR + c) * 2;
        __nv_bfloat162 p;
        p.x = h0; p.y = h1; *(__nv_bfloat162*)(hi + off)     = p;
        p.x = h2; p.y = h3; *(__nv_bfloat162*)(hi + off + 4) = p;
        p.x = l0; p.y = l1; *(__nv_bfloat162*)(lo + off)     = p;
        p.x = l2; p.y = l3; *(__nv_bfloat162*)(lo + off + 4) = p;
    }
}

// ---------------------------------------------------------------------------
// Kernel 0: zero accumulators (deterministic graph replay)
// ---------------------------------------------------------------------------
__global__ void k_zero() {
    int i = blockIdx.x * blockDim.x + threadIdx.x;
    if (i < N_NODES * 32) ((float4*)g_ACC)[i] = make_float4(0.f, 0.f, 0.f, 0.f);
    if (i < N_NODES)      ((float4*)g_D)[i]   = make_float4(0.f, 0.f, 0.f, 0.f);
}

// ---------------------------------------------------------------------------
// Kernel 0b: one-time weight conversion (fp32 -> hi/lo bf16, padded layout)
// ---------------------------------------------------------------------------
__global__ void k_prep(const float* __restrict__ Wq, const float* __restrict__ Wk,
                       const float* __restrict__ Wv, const float* __restrict__ Wsk,
                       const float* __restrict__ We) {
    int i = blockIdx.x * blockDim.x + threadIdx.x;
    if (i < 4 * 16384) {
        int w = i >> 14, j = i & 16383, r = j >> 7, k = j & 127;
        const float* W = (w == 0) ? Wq : (w == 1) ? Wk : (w == 2) ? Wv : Wsk;
        float v = W[j];
        __nv_bfloat16 h = __float2bfloat16(v);
        __nv_bfloat16 l = __float2bfloat16(v - __bfloat162float(h));
        g_Whi[w][r * PSTR + k] = h;
        g_Wlo[w][r * PSTR + k] = l;
    } else if (i < 4 * 16384 + 8192) {
        int j = i - 4 * 16384, r = j >> 6, k = j & 63;
        float v = We[j];
        __nv_bfloat16 h = __float2bfloat16(v);
        __nv_bfloat16 l = __float2bfloat16(v - __bfloat162float(h));
        g_WEhi[r * ESTR + k] = h;
        g_WElo[r * ESTR + k] = l;
    }
}

// ---------------------------------------------------------------------------
// Kernel 1: node projections Q/K/V/skip. 64-row tile (2 CTAs/SM), 8 warps in
// a 2x4 grid; each warp 32 rows x 32 cols via m16n8k16 bf16 HMMA, 3-pass split.
// B tiles staged from pre-converted globals via uint4 copies.
// ---------------------------------------------------------------------------
#define PJ_AT (64 * PSTR * 2)           // 17408 B
#define PJ_BT (128 * PSTR * 2)          // 34816 B
#define PJ_SMEM (2 * PJ_AT + 2 * PJ_BT) // 104448 B -> 2 CTAs/SM

__global__ void __launch_bounds__(256, 2) k_proj(
    const float* __restrict__ x,
    const float* __restrict__ bq, const float* __restrict__ bk,
    const float* __restrict__ bv, const float* __restrict__ bsk,
    float* __restrict__ out)
{
    extern __shared__ char sm[];
    char* AHI = sm;                     char* ALO = sm + PJ_AT;
    char* BHI = sm + 2 * PJ_AT;         char* BLO = sm + 2 * PJ_AT + PJ_BT;
    const uint32_t sAhi = smem_u32(AHI), sAlo = smem_u32(ALO);
    const uint32_t sBhi = smem_u32(BHI), sBlo = smem_u32(BLO);

    const int tid = threadIdx.x, wid = tid >> 5, lane = tid & 31;
    const int row0 = blockIdx.x * 64;
    const int wr = (wid & 1) * 32, wc = (wid >> 1) * 32;

    const int grp = lane >> 3;
    const int lr  = ((grp & 1) << 3) + (lane & 7);
    const int lk  = (grp >> 1) << 3;

    cvt_tile<64, 128, PSTR>(x + (size_t)row0 * 128, N_NODES - row0, AHI, ALO, tid);

    const float* Bptr[4] = {bq, bk, bv, bsk};
    float*       Dptr[4] = {g_Q, g_K, g_V, out};

    for (int w = 0; w < 4; w++) {
        // Stage pre-converted B (hi/lo) via vector copies
        {
            const uint4* shi = (const uint4*)&g_Whi[w][0];
            const uint4* slo = (const uint4*)&g_Wlo[w][0];
            uint4* dhi = (uint4*)BHI;
            uint4* dlo = (uint4*)BLO;
            for (int t = tid; t < PJ_BT / 16; t += 256) {
                dhi[t] = shi[t];
                dlo[t] = slo[t];
            }
        }
        __syncthreads();

        float acc[2][4][4];
#pragma unroll
        for (int mi = 0; mi < 2; mi++)
#pragma unroll
            for (int nj = 0; nj < 4; nj++)
#pragma unroll
                for (int q = 0; q < 4; q++) acc[mi][nj][q] = 0.f;

#pragma unroll
        for (int p = 0; p < 3; p++) {
            const uint32_t sA = (p < 2) ? sAhi : sAlo;
            const uint32_t sB = (p == 1) ? sBlo : sBhi;
#pragma unroll
            for (int k = 0; k < 128; k += 16) {
                uint32_t a[2][4], b[2][4];
#pragma unroll
                for (int mi = 0; mi < 2; mi++)
                    LDSM4(a[mi], sA + ((wr + mi * 16 + lr) * PSTR + k + lk) * 2);
#pragma unroll
                for (int nt = 0; nt < 2; nt++)
                    LDSM4(b[nt], sB + ((wc + nt * 16 + lr) * PSTR + k + lk) * 2);
#pragma unroll
                for (int mi = 0; mi < 2; mi++)
#pragma unroll
                    for (int nt = 0; nt < 2; nt++) {
                        MMA_BF16(acc[mi][nt * 2 + 0], a[mi], b[nt][0], b[nt][2]);
                        MMA_BF16(acc[mi][nt * 2 + 1], a[mi], b[nt][1], b[nt][3]);
                    }
            }
        }

        const int tr = lane >> 2, tc2 = (lane & 3) * 2;
        const float* bias = Bptr[w];
        float* dst = Dptr[w];
#pragma unroll
        for (int mi = 0; mi < 2; mi++) {
            int r = row0 + wr + mi * 16 + tr;
#pragma unroll
            for (int nj = 0; nj < 4; nj++) {
                int col = wc + nj * 8 + tc2;
                float2 b2 = *(const float2*)(bias + col);
                if (r < N_NODES) {
                    float2 o = make_float2(acc[mi][nj][0] + b2.x, acc[mi][nj][1] + b2.y);
                    *(float2*)(dst + (size_t)r * 128 + col) = o;
                }
                if (r + 8 < N_NODES) {
                    float2 o = make_float2(acc[mi][nj][2] + b2.x, acc[mi][nj][3] + b2.y);
                    *(float2*)(dst + (size_t)(r + 8) * 128 + col) = o;
                }
            }
        }
        __syncthreads();
    }
}

// ---------------------------------------------------------------------------
// Kernel 2: edge GEMM e = edge_attr @ We^T (bf16-split HMMA) fused with
// logits, exp, denom atomics and unnormalized message accumulation.
// ---------------------------------------------------------------------------
#define EG_T (128 * ESTR * 2)          // 18432 B per tile
#define EG_SMEM (4 * EG_T)             // 73728 B; e-tile (67584 B) reuses region

__global__ void __launch_bounds__(256) k_edge(
    const float* __restrict__ ea,
    const int*   __restrict__ eidx)
{
    extern __shared__ char sm[];
    char* AHI = sm;            char* ALO = sm + EG_T;
    char* BHI = sm + 2 * EG_T; char* BLO = sm + 3 * EG_T;
    const uint32_t sAhi = smem_u32(AHI), sAlo = smem_u32(ALO);
    const uint32_t sBhi = smem_u32(BHI), sBlo = smem_u32(BLO);
    float* es = (float*)sm;            // e tile [128][132] fp32, reused region

    const int tid = threadIdx.x, wid = tid >> 5, lane = tid & 31;
    const int e0 = blockIdx.x * 128;
    const int wr = (wid & 3) * 32, wc = (wid >> 2) * 64;
    const int grp = lane >> 3;
    const int lr  = ((grp & 1) << 3) + (lane & 7);
    const int lk  = (grp >> 1) << 3;

    cvt_tile<128, 64, ESTR>(ea + (size_t)e0 * 64, N_EDGES - e0, AHI, ALO, tid);
    {
        const uint4* shi = (const uint4*)&g_WEhi[0];
        const uint4* slo = (const uint4*)&g_WElo[0];
        uint4* dhi = (uint4*)BHI;
        uint4* dlo = (uint4*)BLO;
        for (int t = tid; t < EG_T / 16; t += 256) {
            dhi[t] = shi[t];
            dlo[t] = slo[t];
        }
    }
    __syncthreads();

    float acc[2][8][4];
#pragma unroll
    for (int mi = 0; mi < 2; mi++)
#pragma unroll
        for (int nj = 0; nj < 8; nj++)
#pragma unroll
            for (int q = 0; q < 4; q++) acc[mi][nj][q] = 0.f;

#pragma unroll
    for (int p = 0; p < 3; p++) {
        const uint32_t sA = (p < 2) ? sAhi : sAlo;
        const uint32_t sB = (p == 1) ? sBlo : sBhi;
#pragma unroll
        for (int k = 0; k < 64; k += 16) {
            uint32_t a[2][4], b[4][4];
#pragma unroll
            for (int mi = 0; mi < 2; mi++)
                LDSM4(a[mi], sA + ((wr + mi * 16 + lr) * ESTR + k + lk) * 2);
#pragma unroll
            for (int nt = 0; nt < 4; nt++)
                LDSM4(b[nt], sB + ((wc + nt * 16 + lr) * ESTR + k + lk) * 2);
#pragma unroll
            for (int mi = 0; mi < 2; mi++)
#pragma unroll
                for (int nt = 0; nt < 4; nt++) {
                    MMA_BF16(acc[mi][nt * 2 + 0], a[mi], b[nt][0], b[nt][2]);
                    MMA_BF16(acc[mi][nt * 2 + 1], a[mi], b[nt][1], b[nt][3]);
                }
        }
    }
    __syncthreads();   // all smem reads done; safe to overwrite with e tile

    // Spill e tile to smem fp32 [128][132]
    {
        const int tr = lane >> 2, tc2 = (lane & 3) * 2;
#pragma unroll
        for (int mi = 0; mi < 2; mi++) {
            int r = wr + mi * 16 + tr;
#pragma unroll
            for (int nj = 0; nj < 8; nj++) {
                int col = wc + nj * 8 + tc2;
                *(float2*)(es + r * 132 + col) =
                    make_float2(acc[mi][nj][0], acc[mi][nj][1]);
                *(float2*)(es + (r + 8) * 132 + col) =
                    make_float2(acc[mi][nj][2], acc[mi][nj][3]);
            }
        }
    }
    __syncthreads();

    // Epilogue: 8 lanes per edge (4 edges per warp, 4 iterations).
    const int sub = lane >> 3;   // edge-in-group 0..3
    const int li  = lane & 7;
    const float sc = 0.17677669529663687f;  // 1/sqrt(32)

#pragma unroll
    for (int it = 0; it < 4; it++) {
        const int el = wid * 16 + it * 4 + sub;
        const int ed = e0 + el;
        const bool valid = ed < N_EDGES;
        int s = 0, d = 0;
        if (valid) { s = eidx[ed]; d = eidx[N_EDGES + ed]; }

        float4 e4[4], v4[4];
        float p[4];
#pragma unroll
        for (int j = 0; j < 4; j++) {
            e4[j] = *(const float4*)(es + el * 132 + j * 32 + li * 4);
            p[j] = 0.f;
        }
        if (valid) {
            const float* Qr = g_Q + (size_t)d * 128;
            const float* Kr = g_K + (size_t)s * 128;
            const float* Vr = g_V + (size_t)s * 128;
#pragma unroll
            for (int j = 0; j < 4; j++) {
                int c = j * 32 + li * 4;
                float4 q4 = *(const float4*)(Qr + c);
                float4 k4 = *(const float4*)(Kr + c);
                v4[j] = *(const float4*)(Vr + c);
                p[j] = q4.x * (k4.x + e4[j].x) + q4.y * (k4.y + e4[j].y) +
                       q4.z * (k4.z + e4[j].z) + q4.w * (k4.w + e4[j].w);
            }
        }
#pragma unroll
        for (int off = 1; off < 8; off <<= 1) {
#pragma unroll
            for (int j = 0; j < 4; j++)
                p[j] += __shfl_xor_sync(0xffffffffu, p[j], off);
        }
        // Global max-shift cancels exactly in exp/denom; logits are O(3).
        float w[4];
#pragma unroll
        for (int j = 0; j < 4; j++) w[j] = __expf(p[j] * sc);

        if (valid && li == 0) {
            atomicAdd(&g_D[(size_t)d * 4 + 0], w[0]);
            atomicAdd(&g_D[(size_t)d * 4 + 1], w[1]);
            atomicAdd(&g_D[(size_t)d * 4 + 2], w[2]);
            atomicAdd(&g_D[(size_t)d * 4 + 3], w[3]);
        }
        if (valid) {
            float* ap = g_ACC + (size_t)d * 128;
#pragma unroll
            for (int j = 0; j < 4; j++) {
                float mx = (v4[j].x + e4[j].x) * w[j];
                float my = (v4[j].y + e4[j].y) * w[j];
                float mz = (v4[j].z + e4[j].z) * w[j];
                float mw = (v4[j].w + e4[j].w) * w[j];
                asm volatile("red.global.add.v4.f32 [%0], {%1,%2,%3,%4};"
                             :: "l"(ap + j * 32 + li * 4),
                                "f"(mx), "f"(my), "f"(mz), "f"(mw)
                             : "memory");
            }
        }
    }
}

// ---------------------------------------------------------------------------
// Kernel 3: out += g_ACC / (denom + 1e-16)   (skip already in out from k_proj)
// ---------------------------------------------------------------------------
__global__ void k_fin(float* __restrict__ out) {
    int i = blockIdx.x * blockDim.x + threadIdx.x;
    if (i < N_NODES * 32) {
        int n = i >> 5, q = i & 31, h = q >> 3;
        float inv = 1.f / (g_D[(size_t)n * 4 + h] + 1e-16f);
        float4 a = ((const float4*)g_ACC)[i];
        float4 o = ((float4*)out)[i];
        o.x += a.x * inv; o.y += a.y * inv;
        o.z += a.z * inv; o.w += a.w * inv;
        ((float4*)out)[i] = o;
    }
}

// ---------------------------------------------------------------------------
extern "C" void kernel_launch(void* const* d_in, const int* in_sizes, int n_in,
                              void* d_out, int out_size)
{
    const float* x    = (const float*)d_in[0];
    const int*   eidx = (const int*)  d_in[1];
    const float* ea   = (const float*)d_in[2];
    const float* Wq   = (const float*)d_in[3];
    const float* bq   = (const float*)d_in[4];
    const float* Wk   = (const float*)d_in[5];
    const float* bk   = (const float*)d_in[6];
    const float* Wv   = (const float*)d_in[7];
    const float* bv   = (const float*)d_in[8];
    const float* We   = (const float*)d_in[9];
    const float* Wsk  = (const float*)d_in[10];
    const float* bsk  = (const float*)d_in[11];
    float* out = (float*)d_out;

    cudaFuncSetAttribute(k_proj, cudaFuncAttributeMaxDynamicSharedMemorySize, PJ_SMEM);
    cudaFuncSetAttribute(k_edge, cudaFuncAttributeMaxDynamicSharedMemorySize, EG_SMEM);

    k_zero<<<(N_NODES * 32 + 255) / 256, 256>>>();
    k_prep<<<(4 * 16384 + 8192 + 255) / 256, 256>>>(Wq, Wk, Wv, Wsk, We);
    k_proj<<<(N_NODES + 63) / 64, 256, PJ_SMEM>>>(x, bq, bk, bv, bsk, out);
    k_edge<<<(N_EDGES + 127) / 128, 256, EG_SMEM>>>(ea, eidx);
    k_fin<<<(N_NODES * 32 + 255) / 256, 256>>>(out);
}